// round 1
// baseline (speedup 1.0000x reference)
#include <cuda_runtime.h>
#include <cuda_bf16.h>

// x: (B,4) f32 — one float4 per row. Three MLPs 3->4->1; route by x[:,1].
// 4 rows per thread: 4x float4 loads, 1x float4 store. Weights are broadcast
// L1 hits, kept in registers, amortized over the 4 rows.

__global__ __launch_bounds__(256) void Program_72902774882571_kernel(
    const float4* __restrict__ x,
    const float* __restrict__ Ws1, const float* __restrict__ bs1,
    const float* __restrict__ Ws2, const float* __restrict__ bs2,
    const float* __restrict__ Wu1, const float* __restrict__ bu1,
    const float* __restrict__ Wu2, const float* __restrict__ bu2,
    const float* __restrict__ Wd1, const float* __restrict__ bd1,
    const float* __restrict__ Wd2, const float* __restrict__ bd2,
    float4* __restrict__ out, int nquads)
{
    int t = blockIdx.x * blockDim.x + threadIdx.x;
    if (t >= nquads) return;

    float4 xs[4];
#pragma unroll
    for (int r = 0; r < 4; ++r) xs[r] = x[4 * t + r];

    const float* W1p[3] = {Ws1, Wu1, Wd1};
    const float* b1p[3] = {bs1, bu1, bd1};
    const float* W2p[3] = {Ws2, Wu2, Wd2};
    const float* b2p[3] = {bs2, bu2, bd2};

    float z[3][4];
#pragma unroll
    for (int n = 0; n < 3; ++n) {
        float W1[12], b1[4], W2[4];
#pragma unroll
        for (int i = 0; i < 12; ++i) W1[i] = __ldg(W1p[n] + i);
#pragma unroll
        for (int i = 0; i < 4; ++i) b1[i] = __ldg(b1p[n] + i);
#pragma unroll
        for (int i = 0; i < 4; ++i) W2[i] = __ldg(W2p[n] + i);
        float b2 = __ldg(b2p[n]);

#pragma unroll
        for (int r = 0; r < 4; ++r) {
            float x0 = xs[r].x, x1 = xs[r].y, x2 = xs[r].z;
            float acc = b2;
#pragma unroll
            for (int j = 0; j < 4; ++j) {
                // W1 is (fan_in=3, fan_out=4) row-major: W1[i*4+j]
                float h = fmaf(x0, W1[0 * 4 + j],
                          fmaf(x1, W1[1 * 4 + j],
                          fmaf(x2, W1[2 * 4 + j], b1[j])));
                h = fmaxf(h, 0.0f);
                acc = fmaf(h, W2[j], acc);
            }
            z[n][r] = acc;
        }
    }

    float4 res;
    float* rp = &res.x;
#pragma unroll
    for (int r = 0; r < 4; ++r) {
        float sel = xs[r].y;
        float zz = (sel == 0.0f) ? z[0][r] : ((sel == 1.0f) ? z[1][r] : z[2][r]);
        float sig = 1.0f / (1.0f + __expf(-zz));
        bool valid = (sel == 0.0f) || (sel == 1.0f) || (sel == 2.0f);
        rp[r] = valid ? sig : 0.0f;
    }
    out[t] = res;
}

extern "C" void kernel_launch(void* const* d_in, const int* in_sizes, int n_in,
                              void* d_out, int out_size)
{
    const float4* x  = (const float4*)d_in[0];
    const float* Ws1 = (const float*)d_in[1];
    const float* bs1 = (const float*)d_in[2];
    const float* Ws2 = (const float*)d_in[3];
    const float* bs2 = (const float*)d_in[4];
    const float* Wu1 = (const float*)d_in[5];
    const float* bu1 = (const float*)d_in[6];
    const float* Wu2 = (const float*)d_in[7];
    const float* bu2 = (const float*)d_in[8];
    const float* Wd1 = (const float*)d_in[9];
    const float* bd1 = (const float*)d_in[10];
    const float* Wd2 = (const float*)d_in[11];
    const float* bd2 = (const float*)d_in[12];

    int B = in_sizes[0] / 4;          // rows
    int nquads = (B + 3) / 4;         // 4 rows per thread
    int threads = 256;
    int blocks = (nquads + threads - 1) / threads;

    Program_72902774882571_kernel<<<blocks, threads>>>(
        x, Ws1, bs1, Ws2, bs2, Wu1, bu1, Wu2, bu2, Wd1, bd1, Wd2, bd2,
        (float4*)d_out, nquads);
}